// round 12
// baseline (speedup 1.0000x reference)
#include <cuda_runtime.h>
#include <cuda_bf16.h>
#include <cstdint>
#include <math.h>

#define B_SZ 256
#define MDIM 512

// ----------------- scratch (device globals; no allocations allowed) --------
__device__ float         g_img_pre[B_SZ * MDIM];
__device__ float         g_txt_pre[B_SZ * MDIM];
__device__ float         g_img_n [B_SZ * MDIM];      // normalized img, fp32 [b][i]
__device__ __nv_bfloat16 g_txt_bf16[B_SZ * MDIM];    // normalized txt, bf16 [b][j]
__device__ float         g_featsT[MDIM * B_SZ];      // relu(feats+bp), [k][b]

// ----------------- small helpers -------------------------------------------
__device__ __forceinline__ uint32_t smem_addr(const void* p) {
    return (uint32_t)__cvta_generic_to_shared(p);
}
__device__ __forceinline__ void cp_async16(void* dst, const void* src) {
    asm volatile("cp.async.cg.shared.global [%0], [%1], 16;"
                 :: "r"(smem_addr(dst)), "l"(src) : "memory");
}
__device__ __forceinline__ void cp_commit() {
    asm volatile("cp.async.commit_group;" ::: "memory");
}
__device__ __forceinline__ uint32_t pack_bf16x2(float2 v) {
    __nv_bfloat162 h = __float22bfloat162_rn(v);   // .x = low half
    return *reinterpret_cast<uint32_t*>(&h);
}
__device__ __forceinline__ void mma_16816(float c[4], uint32_t a0, uint32_t a1,
                                          uint32_t a2, uint32_t a3,
                                          uint32_t b0, uint32_t b1) {
    asm volatile(
        "mma.sync.aligned.m16n8k16.row.col.f32.bf16.bf16.f32 "
        "{%0,%1,%2,%3}, {%4,%5,%6,%7}, {%8,%9}, {%0,%1,%2,%3};"
        : "+f"(c[0]), "+f"(c[1]), "+f"(c[2]), "+f"(c[3])
        : "r"(a0), "r"(a1), "r"(a2), "r"(a3), "r"(b0), "r"(b1));
}

// ----------------- Phase 1: mapping GEMMs  Out[b,m] = X@W^T + bias ----------
__global__ void __launch_bounds__(256) map_gemm_kernel(
    const float* __restrict__ Xi, const float* __restrict__ Wi, const float* __restrict__ bi,
    const float* __restrict__ Xt, const float* __restrict__ Wt, const float* __restrict__ bt)
{
    const float *X, *W, *bias;
    float* Out;
    if (blockIdx.z == 0) { X = Xi; W = Wi; bias = bi; Out = g_img_pre; }
    else                 { X = Xt; W = Wt; bias = bt; Out = g_txt_pre; }

    __shared__ float As[64][17];
    __shared__ float Bs[64][17];
    const int tid = threadIdx.x;
    const int tx = tid & 15, ty = tid >> 4;
    const int b0 = blockIdx.y * 64, m0 = blockIdx.x * 64;
    float acc[4][4] = {};
    for (int kk = 0; kk < 512; kk += 16) {
        #pragma unroll
        for (int q = 0; q < 4; ++q) {
            int idx = q * 256 + tid;
            int r = idx >> 4, cc = idx & 15;
            As[r][cc] = X[(size_t)(b0 + r) * 512 + kk + cc];
            Bs[r][cc] = W[(size_t)(m0 + r) * 512 + kk + cc];
        }
        __syncthreads();
        #pragma unroll
        for (int k2 = 0; k2 < 16; ++k2) {
            float a[4], bb[4];
            #pragma unroll
            for (int i = 0; i < 4; ++i) a[i] = As[ty * 4 + i][k2];
            #pragma unroll
            for (int j = 0; j < 4; ++j) bb[j] = Bs[tx * 4 + j][k2];
            #pragma unroll
            for (int i = 0; i < 4; ++i)
                #pragma unroll
                for (int j = 0; j < 4; ++j) acc[i][j] = fmaf(a[i], bb[j], acc[i][j]);
        }
        __syncthreads();
    }
    #pragma unroll
    for (int i = 0; i < 4; ++i)
        #pragma unroll
        for (int j = 0; j < 4; ++j)
            Out[(size_t)(b0 + ty * 4 + i) * 512 + m0 + tx * 4 + j] =
                acc[i][j] + bias[m0 + tx * 4 + j];
}

// ----------------- Phase 2: L2 normalize ------------------------------------
__global__ void __launch_bounds__(256) norm_kernel()
{
    __shared__ float red[256];
    const int b = blockIdx.x;
    const int tid = threadIdx.x;

    // image -> g_img_n fp32
    const float* row = g_img_pre + (size_t)b * 512;
    float v0 = row[tid], v1 = row[tid + 256];
    red[tid] = v0 * v0 + v1 * v1;
    __syncthreads();
    for (int o = 128; o > 0; o >>= 1) { if (tid < o) red[tid] += red[tid + o]; __syncthreads(); }
    float s = 1.0f / fmaxf(sqrtf(red[0]), 1e-12f);
    g_img_n[(size_t)b * 512 + tid]       = v0 * s;
    g_img_n[(size_t)b * 512 + tid + 256] = v1 * s;
    __syncthreads();

    // text -> g_txt_bf16
    row = g_txt_pre + (size_t)b * 512;
    v0 = row[tid]; v1 = row[tid + 256];
    red[tid] = v0 * v0 + v1 * v1;
    __syncthreads();
    for (int o = 128; o > 0; o >>= 1) { if (tid < o) red[tid] += red[tid + o]; __syncthreads(); }
    s = 1.0f / fmaxf(sqrtf(red[0]), 1e-12f);
    g_txt_bf16[(size_t)b * 512 + tid]       = __float2bfloat16(v0 * s);
    g_txt_bf16[(size_t)b * 512 + tid + 256] = __float2bfloat16(v1 * s);
}

// ----------------- Phase 3: bilinear head (one CTA per k) -------------------
// smem layout (dynamic):
//   txt: 2 x [256][TXT_PITCH] bf16
//   W  : 2 x [128][W_PITCH]  fp32
//   feats_s: [256] fp32
#define TXT_PITCH 72     // halfs per row (64 data + 8 pad) -> 144 B, 16B multiple
#define W_PITCH   68     // floats per row (64 data + 4 pad) -> 272 B, 16B multiple
#define TXT_BUF_BYTES (256 * TXT_PITCH * 2)     // 36864
#define W_BUF_BYTES   (128 * W_PITCH * 4)       // 34816
#define SMEM_BYTES (2 * TXT_BUF_BYTES + 2 * W_BUF_BYTES + 256 * 4)  // 144384

__global__ void __launch_bounds__(512, 1) blip_bilinear_kernel(
    const float* __restrict__ Wp, const float* __restrict__ bp)
{
    extern __shared__ char smem[];
    __nv_bfloat16* txt_s = (__nv_bfloat16*)smem;                       // [2][256][72]
    float* w_s     = (float*)(smem + 2 * TXT_BUF_BYTES);               // [2][128][68]
    float* feats_s = (float*)(smem + 2 * TXT_BUF_BYTES + 2 * W_BUF_BYTES);

    const int tid  = threadIdx.x;
    const int lane = tid & 31;
    const int warp = tid >> 5;
    const int wb = warp >> 2;      // b block: wb*64
    const int wi = warp & 3;       // i block within pass: wi*32
    const int k = blockIdx.x;
    const float* WpK = Wp + (size_t)k * 512 * 512;

    if (tid < 256) feats_s[tid] = 0.0f;

    // ---- prefetch lambda-ish (macro-free inline) ----
    // step -> pass = step>>3 (i0 = pass*128), jc = step&7 (j0 = jc*64)
    auto prefetch = [&](int step, int buf) {
        const int pass = step >> 3, jc = step & 7;
        const int i0 = pass * 128, j0 = jc * 64;
        // txt chunk: 256 rows x 64 halfs = 2048 x 16B
        #pragma unroll
        for (int t = 0; t < 4; ++t) {
            int idx = tid + t * 512;
            int r = idx >> 3, seg = idx & 7;
            cp_async16(&txt_s[(size_t)buf * 256 * TXT_PITCH + r * TXT_PITCH + seg * 8],
                       g_txt_bf16 + (size_t)r * 512 + j0 + seg * 8);
        }
        // W chunk: 128 rows x 64 floats = 2048 x 16B
        #pragma unroll
        for (int t = 0; t < 4; ++t) {
            int idx = tid + t * 512;
            int r = idx >> 4, seg = idx & 15;
            cp_async16(&w_s[(size_t)buf * 128 * W_PITCH + r * W_PITCH + seg * 4],
                       WpK + (size_t)(i0 + r) * 512 + j0 + seg * 4);
        }
    };

    float c[4][4][4];   // [mfrag][nfrag][4]

    prefetch(0, 0);
    cp_commit();

    int buf = 0;
    for (int step = 0; step < 32; ++step) {
        const int pass = step >> 3, jc = step & 7;

        if (step + 1 < 32) { prefetch(step + 1, buf ^ 1); cp_commit(); }

        if (step + 1 < 32) asm volatile("cp.async.wait_group 1;" ::: "memory");
        else               asm volatile("cp.async.wait_group 0;" ::: "memory");
        __syncthreads();

        if (jc == 0) {
            #pragma unroll
            for (int mf = 0; mf < 4; ++mf)
                #pragma unroll
                for (int nf = 0; nf < 4; ++nf)
                    #pragma unroll
                    for (int q = 0; q < 4; ++q) c[mf][nf][q] = 0.0f;
        }

        const __nv_bfloat16* tbuf = txt_s + (size_t)buf * 256 * TXT_PITCH;
        const float* wbuf = w_s + (size_t)buf * 128 * W_PITCH;

        #pragma unroll
        for (int js = 0; js < 4; ++js) {
            const int jlo = js * 16 + 2 * (lane & 3);
            // B fragments: B[k=j][n=i] = W[i][j]
            uint32_t bfr[4][2];
            #pragma unroll
            for (int nf = 0; nf < 4; ++nf) {
                const float* wr = wbuf + (size_t)(wi * 32 + nf * 8 + (lane >> 2)) * W_PITCH;
                float2 lo = *(const float2*)(wr + jlo);
                float2 hi = *(const float2*)(wr + jlo + 8);
                bfr[nf][0] = pack_bf16x2(lo);
                bfr[nf][1] = pack_bf16x2(hi);
            }
            #pragma unroll
            for (int mf = 0; mf < 4; ++mf) {
                const int br = wb * 64 + mf * 16 + (lane >> 2);
                const __nv_bfloat16* t0 = tbuf + (size_t)br * TXT_PITCH + jlo;
                uint32_t a0 = *(const uint32_t*)(t0);
                uint32_t a1 = *(const uint32_t*)(t0 + 8 * TXT_PITCH);
                uint32_t a2 = *(const uint32_t*)(t0 + 8);
                uint32_t a3 = *(const uint32_t*)(t0 + 8 * TXT_PITCH + 8);
                #pragma unroll
                for (int nf = 0; nf < 4; ++nf)
                    mma_16816(c[mf][nf], a0, a1, a2, a3, bfr[nf][0], bfr[nf][1]);
            }
        }

        if (jc == 7) {
            // epilogue: feats[b] += sum_i D[b,i] * img[b,i] for this i-pass
            const int i0 = pass * 128;
            #pragma unroll
            for (int mf = 0; mf < 4; ++mf) {
                const int b0 = wb * 64 + mf * 16 + (lane >> 2);
                float p0 = 0.0f, p1 = 0.0f;
                #pragma unroll
                for (int nf = 0; nf < 4; ++nf) {
                    const int icol = i0 + wi * 32 + nf * 8 + 2 * (lane & 3);
                    float2 v0 = *(const float2*)(g_img_n + (size_t)b0 * 512 + icol);
                    float2 v1 = *(const float2*)(g_img_n + (size_t)(b0 + 8) * 512 + icol);
                    p0 += c[mf][nf][0] * v0.x + c[mf][nf][1] * v0.y;
                    p1 += c[mf][nf][2] * v1.x + c[mf][nf][3] * v1.y;
                }
                atomicAdd(&feats_s[b0], p0);
                atomicAdd(&feats_s[b0 + 8], p1);
            }
        }
        __syncthreads();   // all reads of buf done before it is refilled
        buf ^= 1;
    }

    __syncthreads();
    if (tid < 256) {
        float v = feats_s[tid] + bp[k];
        g_featsT[(size_t)k * 256 + tid] = fmaxf(v, 0.0f);
    }
}

// ----------------- Phase 4: classifier + sigmoid ----------------------------
__global__ void __launch_bounds__(256) cls_kernel(
    const float* __restrict__ Wc, const float* __restrict__ bc, float* __restrict__ out)
{
    __shared__ float wcs[512];
    const int tid = threadIdx.x;
    wcs[tid] = Wc[tid];
    wcs[tid + 256] = Wc[tid + 256];
    __syncthreads();
    float acc = bc[0];
    #pragma unroll 8
    for (int k = 0; k < 512; ++k)
        acc += g_featsT[(size_t)k * 256 + tid] * wcs[k];
    out[tid] = 1.0f / (1.0f + expf(-acc));
}

// ----------------- launcher --------------------------------------------------
extern "C" void kernel_launch(void* const* d_in, const int* in_sizes, int n_in,
                              void* d_out, int out_size) {
    const float* image_embeds = (const float*)d_in[0];
    const float* text_embeds  = (const float*)d_in[1];
    const float* Wi = (const float*)d_in[2];
    const float* bi = (const float*)d_in[3];
    const float* Wt = (const float*)d_in[4];
    const float* bt = (const float*)d_in[5];
    const float* Wp = (const float*)d_in[6];
    const float* bp = (const float*)d_in[7];
    const float* Wc = (const float*)d_in[8];
    const float* bc = (const float*)d_in[9];
    float* out = (float*)d_out;

    static bool attr_set = false;
    if (!attr_set) {
        cudaFuncSetAttribute(blip_bilinear_kernel,
                             cudaFuncAttributeMaxDynamicSharedMemorySize, SMEM_BYTES);
        attr_set = true;
    }

    map_gemm_kernel<<<dim3(8, 4, 2), 256>>>(image_embeds, Wi, bi, text_embeds, Wt, bt);
    norm_kernel<<<256, 256>>>();
    blip_bilinear_kernel<<<512, 512, SMEM_BYTES>>>(Wp, bp);
    cls_kernel<<<1, 256>>>(Wc, bc, out);
}

// round 16
// speedup vs baseline: 1.2860x; 1.2860x over previous
#include <cuda_runtime.h>
#include <cuda_bf16.h>
#include <cstdint>
#include <math.h>

#define B_SZ 256
#define MDIM 512

// ----------------- scratch (device globals; no allocations allowed) --------
__device__ float         g_img_pre[B_SZ * MDIM];
__device__ float         g_txt_pre[B_SZ * MDIM];
__device__ float         g_img   [B_SZ * MDIM];      // normalized img fp32 [b][i]
__device__ __nv_bfloat16 g_txt_bf16[B_SZ * MDIM];    // normalized txt bf16 [b][j]
__device__ float         g_part  [2][B_SZ * MDIM];   // bilinear partials [half][b*512+k]

// ----------------- helpers --------------------------------------------------
__device__ __forceinline__ uint32_t smem_u32(const void* p) {
    return (uint32_t)__cvta_generic_to_shared(p);
}
__device__ __forceinline__ void cp_async16(uint32_t dst, const void* src) {
    asm volatile("cp.async.cg.shared.global [%0], [%1], 16;"
                 :: "r"(dst), "l"(src) : "memory");
}
__device__ __forceinline__ void ldsm_x4(uint32_t r[4], uint32_t a) {
    asm volatile("ldmatrix.sync.aligned.m8n8.x4.shared.b16 {%0,%1,%2,%3}, [%4];"
                 : "=r"(r[0]), "=r"(r[1]), "=r"(r[2]), "=r"(r[3]) : "r"(a));
}
__device__ __forceinline__ uint32_t pack_bf16x2(float2 v) {
    __nv_bfloat162 h = __float22bfloat162_rn(v);
    return *reinterpret_cast<uint32_t*>(&h);
}
__device__ __forceinline__ void mma_16816(float c[4], uint32_t a0, uint32_t a1,
                                          uint32_t a2, uint32_t a3,
                                          uint32_t b0, uint32_t b1) {
    asm volatile(
        "mma.sync.aligned.m16n8k16.row.col.f32.bf16.bf16.f32 "
        "{%0,%1,%2,%3}, {%4,%5,%6,%7}, {%8,%9}, {%0,%1,%2,%3};"
        : "+f"(c[0]), "+f"(c[1]), "+f"(c[2]), "+f"(c[3])
        : "r"(a0), "r"(a1), "r"(a2), "r"(a3), "r"(b0), "r"(b1));
}

// ----------------- Phase 1: mapping GEMMs  Out[b,m] = X@W^T + bias ----------
__global__ void __launch_bounds__(256) map_gemm_kernel(
    const float* __restrict__ Xi, const float* __restrict__ Wi, const float* __restrict__ bi,
    const float* __restrict__ Xt, const float* __restrict__ Wt, const float* __restrict__ bt)
{
    const float *X, *W, *bias;
    float* Out;
    if (blockIdx.z == 0) { X = Xi; W = Wi; bias = bi; Out = g_img_pre; }
    else                 { X = Xt; W = Wt; bias = bt; Out = g_txt_pre; }

    __shared__ float As[64][17];
    __shared__ float Bs[64][17];
    const int tid = threadIdx.x;
    const int tx = tid & 15, ty = tid >> 4;
    const int b0 = blockIdx.y * 64, m0 = blockIdx.x * 64;
    float acc[4][4] = {};
    for (int kk = 0; kk < 512; kk += 16) {
        #pragma unroll
        for (int q = 0; q < 4; ++q) {
            int idx = q * 256 + tid;
            int r = idx >> 4, cc = idx & 15;
            As[r][cc] = X[(size_t)(b0 + r) * 512 + kk + cc];
            Bs[r][cc] = W[(size_t)(m0 + r) * 512 + kk + cc];
        }
        __syncthreads();
        #pragma unroll
        for (int k2 = 0; k2 < 16; ++k2) {
            float a[4], bb[4];
            #pragma unroll
            for (int i = 0; i < 4; ++i) a[i] = As[ty * 4 + i][k2];
            #pragma unroll
            for (int j = 0; j < 4; ++j) bb[j] = Bs[tx * 4 + j][k2];
            #pragma unroll
            for (int i = 0; i < 4; ++i)
                #pragma unroll
                for (int j = 0; j < 4; ++j) acc[i][j] = fmaf(a[i], bb[j], acc[i][j]);
        }
        __syncthreads();
    }
    #pragma unroll
    for (int i = 0; i < 4; ++i)
        #pragma unroll
        for (int j = 0; j < 4; ++j)
            Out[(size_t)(b0 + ty * 4 + i) * 512 + m0 + tx * 4 + j] =
                acc[i][j] + bias[m0 + tx * 4 + j];
}

// ----------------- Phase 2: L2 normalize ------------------------------------
__global__ void __launch_bounds__(256) norm_kernel()
{
    __shared__ float red[256];
    const int b = blockIdx.x;
    const int tid = threadIdx.x;

    const float* row = g_img_pre + (size_t)b * 512;
    float v0 = row[tid], v1 = row[tid + 256];
    red[tid] = v0 * v0 + v1 * v1;
    __syncthreads();
    for (int o = 128; o > 0; o >>= 1) { if (tid < o) red[tid] += red[tid + o]; __syncthreads(); }
    float s = 1.0f / fmaxf(sqrtf(red[0]), 1e-12f);
    g_img[(size_t)b * 512 + tid]       = v0 * s;
    g_img[(size_t)b * 512 + tid + 256] = v1 * s;
    __syncthreads();

    row = g_txt_pre + (size_t)b * 512;
    v0 = row[tid]; v1 = row[tid + 256];
    red[tid] = v0 * v0 + v1 * v1;
    __syncthreads();
    for (int o = 128; o > 0; o >>= 1) { if (tid < o) red[tid] += red[tid + o]; __syncthreads(); }
    s = 1.0f / fmaxf(sqrtf(red[0]), 1e-12f);
    g_txt_bf16[(size_t)b * 512 + tid]       = __float2bfloat16(v0 * s);
    g_txt_bf16[(size_t)b * 512 + tid + 256] = __float2bfloat16(v1 * s);
}

// ----------------- Phase 3: bilinear head -----------------------------------
// 1024 CTAs: k = bid>>1, half = bid&1 (i in [half*256, half*256+256)).
// Per CTA: 16 steps = 2 i-passes x 8 j-chunks of 64.
// smem: txt 2x[256][72] bf16 (36864 B each), W 2x[128][68] fp32 (34816 B each),
//       feats_s[256] fp32.
#define TXT_PITCH 72
#define W_PITCH   68
#define TXT_BUF_BYTES (256 * TXT_PITCH * 2)
#define W_BUF_BYTES   (128 * W_PITCH * 4)
#define SMEM_BYTES (2 * TXT_BUF_BYTES + 2 * W_BUF_BYTES + 256 * 4)

__global__ void __launch_bounds__(512, 1) blip_bilinear_kernel(const float* __restrict__ Wp)
{
    extern __shared__ char smem[];
    __nv_bfloat16* txt_s = (__nv_bfloat16*)smem;
    float* w_s     = (float*)(smem + 2 * TXT_BUF_BYTES);
    float* feats_s = (float*)(smem + 2 * TXT_BUF_BYTES + 2 * W_BUF_BYTES);

    const int tid  = threadIdx.x;
    const int lane = tid & 31;
    const int warp = tid >> 5;
    const int wb = warp >> 2;      // b block: wb*64
    const int wi = warp & 3;       // i block within pass: wi*32
    const int k    = blockIdx.x >> 1;
    const int half = blockIdx.x & 1;
    const float* WpK = Wp + (size_t)k * 512 * 512;

    if (tid < 256) feats_s[tid] = 0.0f;

    auto prefetch = [&](int step, int buf) {
        const int pass = half * 2 + (step >> 3);
        const int i0 = pass * 128, j0 = (step & 7) * 64;
        // txt chunk: 256 rows x 64 halfs (8 x 16B per row)
        #pragma unroll
        for (int t = 0; t < 4; ++t) {
            int idx = tid + t * 512;
            int r = idx >> 3, seg = idx & 7;
            cp_async16(smem_u32(&txt_s[(size_t)buf * 256 * TXT_PITCH + r * TXT_PITCH + seg * 8]),
                       g_txt_bf16 + (size_t)r * 512 + j0 + seg * 8);
        }
        // W chunk: 128 rows x 64 floats (16 x 16B per row)
        #pragma unroll
        for (int t = 0; t < 4; ++t) {
            int idx = tid + t * 512;
            int r = idx >> 4, seg = idx & 15;
            cp_async16(smem_u32(&w_s[(size_t)buf * 128 * W_PITCH + r * W_PITCH + seg * 4]),
                       WpK + (size_t)(i0 + r) * 512 + j0 + seg * 4);
        }
    };

    float c[4][4][4];

    prefetch(0, 0);
    asm volatile("cp.async.commit_group;" ::: "memory");

    // per-thread A (ldmatrix) addressing constants
    const int arow = wb * 64 + (lane & 15);              // + mf*16
    const uint32_t acg = (uint32_t)((lane >> 4) * 16);   // bytes (16B column group)

    int buf = 0;
    for (int step = 0; step < 16; ++step) {
        const int jc = step & 7;

        if (step + 1 < 16) { prefetch(step + 1, buf ^ 1); asm volatile("cp.async.commit_group;" ::: "memory"); }
        if (step + 1 < 16) asm volatile("cp.async.wait_group 1;" ::: "memory");
        else               asm volatile("cp.async.wait_group 0;" ::: "memory");
        __syncthreads();

        if (jc == 0) {
            #pragma unroll
            for (int mf = 0; mf < 4; ++mf)
                #pragma unroll
                for (int nf = 0; nf < 4; ++nf)
                    #pragma unroll
                    for (int q = 0; q < 4; ++q) c[mf][nf][q] = 0.0f;
        }

        const uint32_t tbase = smem_u32(txt_s + (size_t)buf * 256 * TXT_PITCH)
                               + (uint32_t)arow * (TXT_PITCH * 2) + acg;
        const float* wbuf = w_s + (size_t)buf * 128 * W_PITCH;

        #pragma unroll
        for (int js = 0; js < 4; ++js) {
            // B fragments: W fp32 -> bf16 pairs (B[k=j][n=i] = W[i][j], K-major)
            uint32_t bfr[4][2];
            const int jlo = js * 16 + 2 * (lane & 3);
            #pragma unroll
            for (int nf = 0; nf < 4; ++nf) {
                const float* wr = wbuf + (size_t)(wi * 32 + nf * 8 + (lane >> 2)) * W_PITCH;
                float2 lo = *(const float2*)(wr + jlo);
                float2 hi = *(const float2*)(wr + jlo + 8);
                bfr[nf][0] = pack_bf16x2(lo);
                bfr[nf][1] = pack_bf16x2(hi);
            }
            // A fragments via ldmatrix.x4 (pitch 144B rows, conflict-free)
            #pragma unroll
            for (int mf = 0; mf < 4; ++mf) {
                uint32_t a[4];
                ldsm_x4(a, tbase + (uint32_t)(mf * 16 * (TXT_PITCH * 2) + js * 32));
                #pragma unroll
                for (int nf = 0; nf < 4; ++nf)
                    mma_16816(c[mf][nf], a[0], a[1], a[2], a[3], bfr[nf][0], bfr[nf][1]);
            }
        }

        if (jc == 7) {
            const int i0 = (half * 2 + (step >> 3)) * 128;
            #pragma unroll
            for (int mf = 0; mf < 4; ++mf) {
                const int b0 = wb * 64 + mf * 16 + (lane >> 2);
                float p0 = 0.0f, p1 = 0.0f;
                #pragma unroll
                for (int nf = 0; nf < 4; ++nf) {
                    const int icol = i0 + wi * 32 + nf * 8 + 2 * (lane & 3);
                    float2 v0 = *(const float2*)(g_img + (size_t)b0 * 512 + icol);
                    float2 v1 = *(const float2*)(g_img + (size_t)(b0 + 8) * 512 + icol);
                    p0 += c[mf][nf][0] * v0.x + c[mf][nf][1] * v0.y;
                    p1 += c[mf][nf][2] * v1.x + c[mf][nf][3] * v1.y;
                }
                p0 += __shfl_xor_sync(0xFFFFFFFF, p0, 1);
                p0 += __shfl_xor_sync(0xFFFFFFFF, p0, 2);
                p1 += __shfl_xor_sync(0xFFFFFFFF, p1, 1);
                p1 += __shfl_xor_sync(0xFFFFFFFF, p1, 2);
                if ((lane & 3) == 0) {
                    atomicAdd(&feats_s[b0], p0);
                    atomicAdd(&feats_s[b0 + 8], p1);
                }
            }
        }
        __syncthreads();
        buf ^= 1;
    }

    __syncthreads();
    if (tid < 256)
        g_part[half][(size_t)tid * 512 + k] = feats_s[tid];
}

// ----------------- Phase 4: bias+relu+classifier+sigmoid (256 blocks) -------
__global__ void __launch_bounds__(512) cls_kernel(
    const float* __restrict__ bp, const float* __restrict__ Wc,
    const float* __restrict__ bc, float* __restrict__ out)
{
    __shared__ float red[16];
    const int b = blockIdx.x;
    const int t = threadIdx.x;
    const size_t idx = (size_t)b * 512 + t;
    float f = g_part[0][idx] + g_part[1][idx] + bp[t];
    float v = fmaxf(f, 0.0f) * Wc[t];
    #pragma unroll
    for (int o = 16; o > 0; o >>= 1) v += __shfl_xor_sync(0xFFFFFFFF, v, o);
    if ((t & 31) == 0) red[t >> 5] = v;
    __syncthreads();
    if (t == 0) {
        float s = bc[0];
        #pragma unroll
        for (int w = 0; w < 16; ++w) s += red[w];
        out[b] = 1.0f / (1.0f + expf(-s));
    }
}

// ----------------- launcher --------------------------------------------------
extern "C" void kernel_launch(void* const* d_in, const int* in_sizes, int n_in,
                              void* d_out, int out_size) {
    const float* image_embeds = (const float*)d_in[0];
    const float* text_embeds  = (const float*)d_in[1];
    const float* Wi = (const float*)d_in[2];
    const float* bi = (const float*)d_in[3];
    const float* Wt = (const float*)d_in[4];
    const float* bt = (const float*)d_in[5];
    const float* Wp = (const float*)d_in[6];
    const float* bp = (const float*)d_in[7];
    const float* Wc = (const float*)d_in[8];
    const float* bc = (const float*)d_in[9];
    float* out = (float*)d_out;

    static bool attr_set = false;
    if (!attr_set) {
        cudaFuncSetAttribute(blip_bilinear_kernel,
                             cudaFuncAttributeMaxDynamicSharedMemorySize, SMEM_BYTES);
        attr_set = true;
    }

    map_gemm_kernel<<<dim3(8, 4, 2), 256>>>(image_embeds, Wi, bi, text_embeds, Wt, bt);
    norm_kernel<<<256, 256>>>();
    blip_bilinear_kernel<<<1024, 512, SMEM_BYTES>>>(Wp);
    cls_kernel<<<256, 512>>>(bp, Wc, bc, out);
}